// round 16
// baseline (speedup 1.0000x reference)
#include <cuda_runtime.h>
#include <cuda_bf16.h>
#include <cstdint>

// ---- constants from the reference ----
#define ELE_FACTOR 332.0637f
#define EWALD_F    1.12837917f
#define EWALD_P    0.3275911f
#define EA0        0.254829592f
#define EA1       -0.284496736f
#define EA2        1.421413741f
#define EA3       -1.453152027f
#define EA4        1.061405429f
#define COUL_BETA  18.7f
#define COUL_R0    2.2f
#define G_EWALD    0.3f
#define R6_SHIFT   8303.765625f   // 4.5^6
#define INV_CUT6   1.0e-6f        // 1/10^6

#define MAX_ATOMS 200000

// packed per-atom data (charge, sqrt(c6), r0, pad). 3.2 MB, L2-resident.
__device__ float4 g_atoms[MAX_ATOMS];

// vectorized pack: 4 atoms per thread
__global__ void pack_atoms_kernel4(const float4* __restrict__ q4,
                                   const float4* __restrict__ c64,
                                   const float4* __restrict__ r04,
                                   int nquads) {
    int i = blockIdx.x * blockDim.x + threadIdx.x;
    if (i < nquads) {
        float4 q = __ldcs(&q4[i]);
        float4 c = __ldcs(&c64[i]);
        float4 r = __ldcs(&r04[i]);
        g_atoms[4 * i + 0] = make_float4(q.x, sqrtf(c.x), r.x, 0.0f);
        g_atoms[4 * i + 1] = make_float4(q.y, sqrtf(c.y), r.y, 0.0f);
        g_atoms[4 * i + 2] = make_float4(q.z, sqrtf(c.z), r.z, 0.0f);
        g_atoms[4 * i + 3] = make_float4(q.w, sqrtf(c.w), r.w, 0.0f);
    }
}

// scalar pack for the tail / unaligned case
__global__ void pack_atoms_kernel(const float* __restrict__ q,
                                  const float* __restrict__ c6,
                                  const float* __restrict__ r0,
                                  int n, int start) {
    int i = start + blockIdx.x * blockDim.x + threadIdx.x;
    if (i < n) {
        g_atoms[i] = make_float4(q[i], sqrtf(c6[i]), r0[i], 0.0f);
    }
}

// Per-edge physics from pre-reduced pair scalars.
// qq = qi*qj, c6ij = sqrt(c6i)*sqrt(c6j), r0s = r0i + r0j.
__device__ __forceinline__ void edge_compute(
    float dx, float dy, float dz, float qq, float c6ij, float r0s,
    float& ecoul, float& edisp, float& fc, float& fd)
{
    float r2     = dx * dx + dy * dy + dz * dz;
    float rinv   = rsqrtf(r2);
    float rij    = r2 * rinv;
    float inv_r2 = rinv * rinv;

    // ---------------- Coulomb ----------------
    float prefactor = ELE_FACTOR * qq * rinv;

    float x  = (COUL_BETA / COUL_R0) * (rij - COUL_R0);
    float ex = __expf(-fabsf(x));                     // in (0, 1]
    float inv1pex = __fdividef(1.0f, 1.0f + ex);
    float damp = (x >= 0.0f) ? inv1pex : (ex * inv1pex);   // stable sigmoid
    // softplus(x)/beta, stable
    float sp = (fmaxf(x, 0.0f) + __logf(1.0f + ex)) * (1.0f / COUL_BETA);
    float s  = rij * (1.0f / COUL_R0) * __fdividef(1.0f, 1.0f + sp);

    // Ewald short-range erfc correction
    float grij  = G_EWALD * rij;
    float expm2 = __expf(-grij * grij);
    float t     = __fdividef(1.0f, 1.0f + EWALD_P * grij);
    float erfc  = t * (EA0 + t * (EA1 + t * (EA2 + t * (EA3 + t * EA4)))) * expm2;

    ecoul = prefactor * (s + (erfc - 1.0f));
    float fcoul = prefactor * (damp * s * s + erfc + EWALD_F * grij * expm2 - 1.0f);
    fc = fcoul * inv_r2;

    // ---------------- Dispersion (D3-CSO) ----------------
    float r6     = r2 * r2 * r2 + R6_SHIFT;
    float inv_r6 = __fdividef(1.0f, r6);
    float e      = __expf(rij - 1.25f * r0s);          // rij - 2.5*r0ij
    float inv1pe = __fdividef(1.0f, 1.0f + e);
    float cso    = 0.85f + 0.82f * inv1pe;

    edisp = -c6ij * inv_r6 * cso + c6ij * INV_CUT6;
    float r5    = r2 * r2 * rij;
    float fdisp = -6.0f * c6ij * r5 * inv_r6 * inv_r6 * cso
                  - c6ij * inv_r6 * (0.82f * e * inv1pe * inv1pe);
    fd = fdisp * rinv;
}

__device__ __forceinline__ uint32_t smem_u32(const void* p) {
    uint32_t a;
    asm("{ .reg .u64 t; cvta.to.shared.u64 t, %1; cvt.u32.u64 %0, t; }"
        : "=r"(a) : "l"(p));
    return a;
}

__device__ __forceinline__ void mbar_wait_parity0(uint32_t mbar) {
    asm volatile(
        "{\n\t"
        ".reg .pred P;\n\t"
        "WAIT_%=:\n\t"
        "mbarrier.try_wait.parity.acquire.cta.shared::cta.b64 P, [%0], 0;\n\t"
        "@P bra.uni DONE_%=;\n\t"
        "bra.uni WAIT_%=;\n\t"
        "DONE_%=:\n\t"
        "}" :: "r"(mbar) : "memory");
}

// TMA-staged edge kernel: 128 edges per 128-thread block.
// dij arrives via cp.async.bulk (no per-warp L1TEX wavefronts on the global
// side); each thread LDS-reads its 3 floats (stride-3 = conflict-free).
// cf/df are STS'd to smem (conflict-free) and leave via bulk stores.
// Gathers overlap the TMA load latency. Requires E % 4 == 0; the launched
// range must be a multiple of 128 edges.
__global__ void __launch_bounds__(128)
bamboo_edge_tma(const int*   __restrict__ row,
                const int*   __restrict__ col,
                const float* __restrict__ dij,
                float*       __restrict__ out,
                int E) {
    __shared__ alignas(16) float s_dij[384];   // 1536 B
    __shared__ alignas(16) float s_cf[384];
    __shared__ alignas(16) float s_df[384];
    __shared__ alignas(8)  unsigned long long s_mbar;

    int tid = threadIdx.x;
    int eb  = blockIdx.x * 128;        // first edge of this block
    int i   = eb + tid;

    uint32_t mbar = smem_u32(&s_mbar);
    uint32_t sdij = smem_u32(s_dij);

    if (tid == 0) {
        asm volatile("mbarrier.init.shared.b64 [%0], 1;" :: "r"(mbar) : "memory");
    }
    __syncthreads();
    if (tid == 0) {
        asm volatile("mbarrier.arrive.expect_tx.shared.b64 _, [%0], %1;"
                     :: "r"(mbar), "r"(1536u) : "memory");
        asm volatile("cp.async.bulk.shared::cta.global.mbarrier::complete_tx::bytes "
                     "[%0], [%1], %2, [%3];"
                     :: "r"(sdij), "l"(dij + (size_t)3 * eb), "r"(1536), "r"(mbar)
                     : "memory");
    }

    // overlap TMA with index loads + gathers
    int ri = __ldcs(&row[i]);
    int ci = __ldcs(&col[i]);
    float4 A = __ldcg(&g_atoms[ri]);
    float4 B = __ldcg(&g_atoms[ci]);

    mbar_wait_parity0(mbar);

    float dx = s_dij[3 * tid + 0];
    float dy = s_dij[3 * tid + 1];
    float dz = s_dij[3 * tid + 2];

    float qq = A.x * B.x, c6ij = A.y * B.y, r0s = A.z + B.z;
    float ec, ed, fc, fd;
    edge_compute(dx, dy, dz, qq, c6ij, r0s, ec, ed, fc, fd);

    // energies: coalesced scalar stores (already at the line floor)
    __stcs(&out[i], ec);
    __stcs(&out[(size_t)4 * E + i], ed);

    // forces into smem (stride-3, conflict-free), then bulk store out
    s_cf[3 * tid + 0] = dx * fc;
    s_cf[3 * tid + 1] = dy * fc;
    s_cf[3 * tid + 2] = dz * fc;
    s_df[3 * tid + 0] = dx * fd;
    s_df[3 * tid + 1] = dy * fd;
    s_df[3 * tid + 2] = dz * fd;
    __syncthreads();

    if (tid == 0) {
        uint32_t scf = smem_u32(s_cf);
        uint32_t sdf = smem_u32(s_df);
        float* cf_dst = out + (size_t)E + (size_t)3 * eb;
        float* df_dst = out + (size_t)5 * E + (size_t)3 * eb;
        asm volatile("fence.proxy.async.shared::cta;" ::: "memory");
        asm volatile("cp.async.bulk.global.shared::cta.bulk_group [%0], [%1], %2;"
                     :: "l"(cf_dst), "r"(scf), "r"(1536) : "memory");
        asm volatile("cp.async.bulk.global.shared::cta.bulk_group [%0], [%1], %2;"
                     :: "l"(df_dst), "r"(sdf), "r"(1536) : "memory");
        asm volatile("cp.async.bulk.commit_group;" ::: "memory");
        asm volatile("cp.async.bulk.wait_group 0;" ::: "memory");
    }
}

// scalar fallback/tail: handles edges [start, E)
__global__ void bamboo_edge_tail(const int*   __restrict__ row,
                                 const int*   __restrict__ col,
                                 const float* __restrict__ dij,
                                 float*       __restrict__ out,
                                 int E, int start) {
    int i = start + blockIdx.x * blockDim.x + threadIdx.x;
    if (i >= E) return;
    float dx = dij[3 * i + 0], dy = dij[3 * i + 1], dz = dij[3 * i + 2];
    float4 A = __ldcg(&g_atoms[row[i]]);
    float4 B = __ldcg(&g_atoms[col[i]]);
    float ecoul, edisp, fc, fd;
    edge_compute(dx, dy, dz, A.x * B.x, A.y * B.y, A.z + B.z,
                 ecoul, edisp, fc, fd);
    out[i] = ecoul;
    float* cf = out + (size_t)E + 3 * i;
    cf[0] = dx * fc; cf[1] = dy * fc; cf[2] = dz * fc;
    out[(size_t)4 * E + i] = edisp;
    float* df = out + (size_t)5 * E + 3 * i;
    df[0] = dx * fd; df[1] = dy * fd; df[2] = dz * fd;
}

extern "C" void kernel_launch(void* const* d_in, const int* in_sizes, int n_in,
                              void* d_out, int out_size) {
    const int*   row    = (const int*)d_in[0];
    const int*   col    = (const int*)d_in[1];
    const float* dij    = (const float*)d_in[2];
    const float* charge = (const float*)d_in[3];
    const float* c6     = (const float*)d_in[4];
    const float* r0     = (const float*)d_in[5];
    float* out = (float*)d_out;

    int E = in_sizes[0];
    int N = in_sizes[3];

    // ---- pack atom table ----
    {
        const int tpb = 256;
        int nq = N >> 2;
        if (nq > 0) {
            pack_atoms_kernel4<<<(nq + tpb - 1) / tpb, tpb>>>(
                (const float4*)charge, (const float4*)c6, (const float4*)r0, nq);
        }
        int done = nq << 2;
        if (done < N) {
            pack_atoms_kernel<<<1, tpb>>>(charge, c6, r0, N, done);
        }
    }

    // ---- edge kernel ----
    const int tpb = 128;
    if ((E & 3) == 0) {
        int nblocks = E / 128;               // full 128-edge blocks
        if (nblocks > 0) {
            bamboo_edge_tma<<<nblocks, tpb>>>(row, col, dij, out, E);
        }
        int done = nblocks * 128;
        if (done < E) {
            bamboo_edge_tail<<<1, tpb>>>(row, col, dij, out, E, done);
        }
    } else {
        // alignment fallback: plain scalar over everything
        bamboo_edge_tail<<<(E + tpb - 1) / tpb, tpb>>>(row, col, dij, out, E, 0);
    }
}